// round 17
// baseline (speedup 1.0000x reference)
#include <cuda_runtime.h>
#include <cstdint>

#define S   2048
#define F   512
#define B   32
#define RAD 12
#define KW  25
#define NTILES (S / 32)   // 64 row-tiles

typedef unsigned long long ull;

// ---------------- scratch (device globals: no allocations allowed) ----------
__device__ float g_sp[S];         // softplus(tanh(MLP)) per s
__device__ int   g_i0[S];
__device__ float g_frac[S];
__device__ int   g_slo[NTILES];   // first s whose i0 falls in tile
__device__ int   g_scnt[NTILES];  // number of such s

// Gaussian taps (sigma=3, radius=12, normalized)
__device__ constexpr float KERN[KW] = {
    4.46116e-05f, 1.60100e-04f, 5.14120e-04f, 1.47730e-03f, 3.79880e-03f,
    8.74080e-03f, 1.799760e-02f, 3.316010e-02f, 5.467130e-02f, 8.065920e-02f,
    1.0648560e-01f, 1.2579790e-01f, 1.3298450e-01f, 1.2579790e-01f, 1.0648560e-01f,
    8.065920e-02f, 5.467130e-02f, 3.316010e-02f, 1.799760e-02f, 8.74080e-03f,
    3.79880e-03f, 1.47730e-03f, 5.14120e-04f, 1.60100e-04f, 4.46116e-05f
};

__device__ __forceinline__ int reflect_idx(int r) {
    if (r < 0)       r = -1 - r;
    else if (r >= S) r = 2 * S - 1 - r;
    return r;
}

// packed-pair helpers (each half is IEEE fma.rn — bitwise == scalar fmaf)
__device__ __forceinline__ ull pack_tap(float k) {
    ull t; asm("mov.b64 %0, {%1, %1};" : "=l"(t) : "f"(k)); return t;
}
__device__ __forceinline__ void fma2(ull& a, ull v, ull t) {
    asm("fma.rn.f32x2 %0, %1, %2, %0;" : "+l"(a) : "l"(v), "l"(t));
}

// cp.async 16B helper
__device__ __forceinline__ void cpasync16(uint32_t smem_addr, const void* src) {
    asm volatile("cp.async.cg.shared.global [%0], [%1], 16;"
                 :: "r"(smem_addr), "l"(src));
}

// ---------------- kernel A0: MLP + softplus, parallel across 16 blocks ------
__global__ void __launch_bounds__(128) mlp_kernel(
        const float* __restrict__ W1,
        const float* __restrict__ b1,
        const float* __restrict__ W2,
        const float* __restrict__ b2) {
    __shared__ float sW1[64], sB1[64], sW2[64];
    __shared__ float sB2;
    const int t = threadIdx.x;
    if (t < 64) { sW1[t] = W1[t]; sB1[t] = b1[t]; sW2[t] = W2[t]; }
    if (t == 64) sB2 = b2[0];
    __syncthreads();

    const int s = blockIdx.x * 128 + t;
    const float delta = 1.0f / 2047.0f;
    float tt = (s == S - 1) ? 1.0f : __fmul_rn((float)s, delta);
    float acc = 0.0f;
    for (int j = 0; j < 64; j++) {
        float h = __fadd_rn(__fmul_rn(tt, sW1[j]), sB1[j]);
        h = fmaxf(h, 0.0f);
        acc = __fadd_rn(acc, __fmul_rn(h, sW2[j]));
    }
    float w  = tanhf(__fadd_rn(acc, sB2));
    g_sp[s]  = __fadd_rn(fmaxf(w, 0.0f), log1pf(expf(-fabsf(w))));
}

// ---------------- kernel A1: scan + tables + loss (1 block, 256 thr) --------
#define WT 256
__global__ void __launch_bounds__(WT) scan_kernel(float* __restrict__ out_loss) {
    __shared__ float lev[4095];
    __shared__ float warps[S];
    __shared__ int   si0[S];
    __shared__ float red[WT];

    const int t = threadIdx.x;

    int off[12];
    {
        int o = 0;
        #pragma unroll
        for (int l = 0; l < 12; l++) { off[l] = o; o += (2048 >> l); }
    }

    for (int s = t; s < S; s += WT) lev[off[0] + s] = g_sp[s];

    for (int l = 0; l < 11; l++) {
        __syncthreads();
        const float* src = lev + off[l];
        float*       dst = lev + off[l + 1];
        const int n_next = 2048 >> (l + 1);
        for (int k = t; k < n_next; k += WT)
            dst[k] = __fadd_rn(src[2 * k], src[2 * k + 1]);
    }
    __syncthreads();

    for (int l = 10; l >= 0; l--) {
        float*       Ll  = lev + off[l];
        const float* Sl1 = lev + off[l + 1];
        const int half = 2048 >> (l + 1);
        for (int k = t; k < half; k += WT) {
            float odd_val  = Sl1[k];
            float even_val = (k == 0) ? Ll[0] : __fadd_rn(Sl1[k - 1], Ll[2 * k]);
            Ll[2 * k]     = even_val;
            Ll[2 * k + 1] = odd_val;
        }
        __syncthreads();
    }

    const float T = lev[S - 1];

    for (int s = t; s < S; s += WT)
        warps[s] = __fdiv_rn(lev[s], T);
    __syncthreads();

    for (int s = t; s < S; s += WT) {
        float pos = __fmul_rn(warps[s], (float)(S - 1));
        float fi  = floorf(pos);
        fi = fminf(fmaxf(fi, 0.0f), (float)(S - 2));
        int i0 = (int)fi;
        g_i0[s]   = i0;
        si0[s]    = i0;
        g_frac[s] = __fadd_rn(pos, -fi);
    }
    __syncthreads();

    if (t < NTILES) {
        int lo_val = 32 * t;
        int a = 0, bnd = S;
        while (a < bnd) { int m = (a + bnd) >> 1; if (si0[m] < lo_val) a = m + 1; else bnd = m; }
        int s_lo = a;
        int hi_val = lo_val + 32;
        a = s_lo; bnd = S;
        while (a < bnd) { int m = (a + bnd) >> 1; if (si0[m] < hi_val) a = m + 1; else bnd = m; }
        g_slo[t]  = s_lo;
        g_scnt[t] = a - s_lo;
    }

    float lsum = 0.0f;
    for (int m = t; m < S - 2; m += WT) {
        float d1a = __fadd_rn(warps[m + 1], -warps[m]);
        float d1b = __fadd_rn(warps[m + 2], -warps[m + 1]);
        float d2  = __fadd_rn(d1b, -d1a);
        lsum = fmaf(d2, d2, lsum);
    }
    red[t] = lsum;
    __syncthreads();
    for (int o2 = WT / 2; o2 > 0; o2 >>= 1) {
        if (t < o2) red[t] += red[t + o2];
        __syncthreads();
    }
    if (t == 0) *out_loss = red[0] / (float)(S - 2);
}

// ---------------- fused smooth + interp (cp.async stage + f32x2 conv) -------
// Block = 256 thr = 4 quarters x 64 ull-columns (FL = 128 f). Phase 1: bulk
// cp.async of the 57 input rows (reflect folded into source addresses).
// Phase 2: f32x2 sliding-window conv sourced from smem (LDS latency 29cyc is
// fully covered by the 8-step lookahead — stall-free issue). Phase 3: interp.

#define FL 128
#define NIN (32 + 2 * RAD + 1)   // 57 staged input rows
#define MAXCNT 144

template<int CHT>
__device__ __forceinline__ void conv2_smem(const float* __restrict__ p,  // smem
                                           float* __restrict__ dst) {
    constexpr int NVT = CHT + KW - 1;
    ull vv[NVT];
    #pragma unroll
    for (int i = 0; i < CHT; i++)
        vv[i] = *(const ull*)(p + i * FL);
    ull acc[CHT];
    #pragma unroll
    for (int j = 0; j < CHT; j++) acc[j] = 0ULL;

    #pragma unroll
    for (int m = 0; m < KW; m++) {
        if (m + CHT < NVT)
            vv[m + CHT] = *(const ull*)(p + (m + CHT) * FL);
        const ull tap = pack_tap(KERN[m]);
        #pragma unroll
        for (int j = 0; j < CHT; j++) fma2(acc[j], vv[m + j], tap);
    }
    #pragma unroll
    for (int j = 0; j < CHT; j++)
        *(ull*)(dst + j * FL) = acc[j];
}

__global__ void __launch_bounds__(256, 4) fused_kernel(const float* __restrict__ x,
                                                       float* __restrict__ out) {
    __shared__ float in_stage[NIN * FL];    // 29184 B
    __shared__ float out_stage[33 * FL];    // 16896 B
    __shared__ int   sm_ro[MAXCNT];
    __shared__ float sm_fr[MAXCNT];

    const int tx = threadIdx.x;
    const int r0 = blockIdx.x * 32;
    const int f0 = blockIdx.y * FL;
    const int b  = blockIdx.z;

    // ---- phase 1: bulk async load of input rows (reflect in addresses) ----
    const float* xbase = x + (size_t)b * (S * F) + f0;
    const uint32_t in_base = (uint32_t)__cvta_generic_to_shared(in_stage);
    #pragma unroll 2
    for (int u = tx; u < NIN * (FL / 4); u += 256) {   // 16B units
        const int i = u >> 5;          // staged row
        const int c = u & 31;          // 16B column
        const int r = reflect_idx(r0 - RAD + i);
        cpasync16(in_base + (uint32_t)(i * FL + c * 4) * 4,
                  xbase + (size_t)r * F + c * 4);
    }
    asm volatile("cp.async.commit_group;");

    // metadata loads overlap the bulk copy
    const int s_lo = g_slo[blockIdx.x];
    const int cnt  = g_scnt[blockIdx.x];
    for (int u = tx; u < cnt; u += 256) {
        sm_ro[u] = __ldg(g_i0 + s_lo + u) - r0;
        sm_fr[u] = __ldg(g_frac + s_lo + u);
    }

    asm volatile("cp.async.wait_group 0;" ::: "memory");
    __syncthreads();

    // ---- phase 2: conv from smem ----
    const int col     = tx & 63;       // ull column (2 f)
    const int quarter = tx >> 6;       // 0..3 -> rows quarter*8 .. (+8/9)
    const float* p = in_stage + (quarter * 8) * FL + col * 2;
    float* dst     = out_stage + (quarter * 8) * FL + col * 2;
    if (quarter < 3) conv2_smem<8>(p, dst);
    else             conv2_smem<9>(p, dst);
    __syncthreads();

    // ---- phase 3: interp; outputs s with i0 in [r0, r0+31] ----
    const int nunits = cnt * (FL / 4);
    for (int u = tx; u < nunits; u += 256) {
        const int ui   = u >> 5;
        const int s    = s_lo + ui;
        const int col4 = u & 31;
        const int ro   = sm_ro[ui];
        const float fr = sm_fr[ui];
        const float om = 1.0f - fr;

        const float4 a = ((const float4*)(out_stage + ro * FL))[col4];
        const float4 c = ((const float4*)(out_stage + (ro + 1) * FL))[col4];
        float4 o;
        o.x = a.x * om + c.x * fr;
        o.y = a.y * om + c.y * fr;
        o.z = a.z * om + c.z * fr;
        o.w = a.w * om + c.w * fr;
        ((float4*)(out + ((size_t)(b * S + s) * F + f0)))[col4] = o;
    }
}

// ---------------- launch ----------------------------------------------------
extern "C" void kernel_launch(void* const* d_in, const int* in_sizes, int n_in,
                              void* d_out, int out_size) {
    const float* x  = (const float*)d_in[0];
    const float* W1 = (const float*)d_in[1];
    const float* b1 = (const float*)d_in[2];
    const float* W2 = (const float*)d_in[3];
    const float* b2 = (const float*)d_in[4];
    float* out = (float*)d_out;

    mlp_kernel<<<S / 128, 128>>>(W1, b1, W2, b2);
    // loss scalar is the last output element
    scan_kernel<<<1, WT>>>(out + (out_size - 1));

    dim3 gridF(NTILES, F / FL, B);
    fused_kernel<<<gridF, 256>>>(x, out);
}